// round 4
// baseline (speedup 1.0000x reference)
#include <cuda_runtime.h>

#define TILE 128
#define MAX_TILES 64   // supports N up to 8192

// Per-block partial sums (deterministic reduction; no atomics, no allocations).
__device__ double g_partials[MAX_TILES * MAX_TILES];

__global__ void wrnl_pair_kernel(const float* __restrict__ logits,
                                 const int* __restrict__ rankings,  // JAX x64 disabled -> int32
                                 int n) {
    const int ti = blockIdx.y;
    const int tj = blockIdx.x;
    const int nt = gridDim.x;
    const int bid = ti * nt + tj;
    const int t = threadIdx.x;   // 128 threads; thread t owns row i = ti*TILE + t

    if (tj < ti) {               // lower triangle: no work, but must write its partial
        if (t == 0) g_partials[bid] = 0.0;
        return;
    }

    __shared__ float2 sJ[TILE];  // {logit_j, rank_j (as float, exact for <2^24)}

    const int gi = ti * TILE + t;
    const int gj = tj * TILE + t;

    float li, ri;
    if (gi < n) {
        li = logits[gi];
        ri = (float)rankings[gi];
    } else {
        li = 0.0f;
        ri = 3.0e9f;             // never satisfies ri < rj -> inactive
    }
    if (gj < n) {
        sJ[t] = make_float2(logits[gj], (float)rankings[gj]);
    } else {
        sJ[t] = make_float2(0.0f, -1.0f);   // rj = -1 -> ri < rj false -> inactive
    }
    __syncthreads();

    float acc = 0.0f;
    const bool diag = (ti == tj);

    #pragma unroll 8
    for (int j = 0; j < TILE; ++j) {
        float2 lr = sJ[j];                   // LDS.64, broadcast across the warp
        float d  = lr.x - li;                // logits[j] - logits[i]
        // stable softplus: max(d,0) + log1p(exp(-|d|)); e in (0,1]
        float e  = __expf(0.0f - fabsf(d));  // MUFU.EX2 path
        float sp = fmaxf(d, 0.0f) + __logf(1.0f + e);  // MUFU.LG2 path
        float rs = ri + lr.y;                // r_i + r_j (>=1 for any active pair)
        float w;
        asm("rcp.approx.f32 %0, %1;" : "=f"(w) : "f"(rs));  // single MUFU.RCP
        bool act = (ri < lr.y);
        if (diag) act = act && (t < j);      // enforce i<j on the diagonal tile
        float wsel = act ? w : 0.0f;         // SEL; kills inf from rs==0 too
        acc = fmaf(sp, wsel, acc);
    }

    // Block reduction: 4 warps -> double partial (deterministic)
    __shared__ float warpSum[4];
    #pragma unroll
    for (int off = 16; off > 0; off >>= 1)
        acc += __shfl_down_sync(0xffffffffu, acc, off);
    if ((t & 31) == 0) warpSum[t >> 5] = acc;
    __syncthreads();
    if (t == 0) {
        double s = (double)warpSum[0] + (double)warpSum[1]
                 + (double)warpSum[2] + (double)warpSum[3];
        g_partials[bid] = s;
    }
}

__global__ void wrnl_reduce_kernel(float* __restrict__ out, int n, int nblocks) {
    __shared__ double sm[256];
    double a = 0.0;
    for (int i = (int)threadIdx.x; i < nblocks; i += (int)blockDim.x)
        a += g_partials[i];
    sm[threadIdx.x] = a;
    __syncthreads();
    for (int s = 128; s > 0; s >>= 1) {
        if ((int)threadIdx.x < s) sm[threadIdx.x] += sm[threadIdx.x + s];
        __syncthreads();
    }
    if (threadIdx.x == 0) out[0] = (float)(sm[0] / (double)n);
}

extern "C" void kernel_launch(void* const* d_in, const int* in_sizes, int n_in,
                              void* d_out, int out_size) {
    const float* logits   = (const float*)d_in[0];
    const int*   rankings = (const int*)d_in[1];
    int n  = in_sizes[0];
    int nt = (n + TILE - 1) / TILE;          // 64 for N=8192

    dim3 grid(nt, nt);
    wrnl_pair_kernel<<<grid, TILE>>>(logits, rankings, n);
    wrnl_reduce_kernel<<<1, 256>>>((float*)d_out, n, nt * nt);
}

// round 5
// speedup vs baseline: 1.3779x; 1.3779x over previous
#include <cuda_runtime.h>

#define TILE 128
#define MAX_TILES 64                       // N up to 8192
#define MAX_BLOCKS (MAX_TILES * (MAX_TILES + 1) / 2)   // 2080

// Per-block partial sums + completion counter (no allocations, deterministic).
__device__ double g_partials[MAX_BLOCKS];
__device__ int    g_count = 0;

__device__ __forceinline__ float ex2_approx(float x) {
    float r; asm("ex2.approx.f32 %0, %1;" : "=f"(r) : "f"(x)); return r;
}
__device__ __forceinline__ float lg2_approx(float x) {
    float r; asm("lg2.approx.f32 %0, %1;" : "=f"(r) : "f"(x)); return r;
}
__device__ __forceinline__ float rcp_approx(float x) {
    float r; asm("rcp.approx.f32 %0, %1;" : "=f"(r) : "f"(x)); return r;
}

__global__ void __launch_bounds__(TILE)
wrnl_kernel(const float* __restrict__ logits,
            const int* __restrict__ rankings,   // JAX default x64-disabled -> int32
            float* __restrict__ out,
            int n, int nt, int nblocks) {
    const int t = threadIdx.x;

    // ---- decode triangular block index k -> (ti, tj), ti <= tj ----
    const int k = blockIdx.x;
    float b = 2.0f * (float)nt + 1.0f;
    int ti = (int)((b - sqrtf(b * b - 8.0f * (float)k)) * 0.5f);
    while (ti > 0 && k < ti * nt - (ti * (ti - 1)) / 2) --ti;
    while (k >= (ti + 1) * nt - ((ti + 1) * ti) / 2) ++ti;
    const int tj = ti + (k - (ti * nt - (ti * (ti - 1)) / 2));

    __shared__ float2 sJ[TILE];              // {logit_j, rank_j as float (exact < 2^24)}

    const int gi = ti * TILE + t;
    const int gj = tj * TILE + t;

    float li, ri;
    if (gi < n) { li = logits[gi]; ri = (float)rankings[gi]; }
    else        { li = 0.0f;       ri = 3.0e9f; }            // never active
    if (gj < n) sJ[t] = make_float2(logits[gj], (float)rankings[gj]);
    else        sJ[t] = make_float2(0.0f, -1.0f);            // rj=-1 -> inactive
    __syncthreads();

    const float LN2 = 0.69314718055994531f;
    const float NL2E = -1.44269504088896340f;                // -log2(e)

    float acc0 = 0.0f, acc1 = 0.0f;

    if (ti != tj) {
        // off-diagonal: every (i,j) has i<j globally; only rank test needed
        #pragma unroll 16
        for (int j = 0; j < TILE; ++j) {
            float2 lr = sJ[j];                       // LDS.64 broadcast
            float d  = lr.x - li;
            float e  = ex2_approx(fabsf(d) * NL2E);  // exp(-|d|), 1 MUFU
            float lg = lg2_approx(1.0f + e);         // log2(1+e), 1 MUFU
            float sp = fmaf(lg, LN2, fmaxf(d, 0.0f));
            float w  = rcp_approx(ri + lr.y);        // 1 MUFU
            float ws = (ri < lr.y) ? w : 0.0f;
            if (j & 1) acc1 = fmaf(sp, ws, acc1);
            else       acc0 = fmaf(sp, ws, acc0);
        }
    } else {
        // diagonal tile: additionally require t < j
        #pragma unroll 16
        for (int j = 0; j < TILE; ++j) {
            float2 lr = sJ[j];
            float d  = lr.x - li;
            float e  = ex2_approx(fabsf(d) * NL2E);
            float lg = lg2_approx(1.0f + e);
            float sp = fmaf(lg, LN2, fmaxf(d, 0.0f));
            float w  = rcp_approx(ri + lr.y);
            float ws = ((ri < lr.y) && (t < j)) ? w : 0.0f;
            if (j & 1) acc1 = fmaf(sp, ws, acc1);
            else       acc0 = fmaf(sp, ws, acc0);
        }
    }

    // ---- block reduction to one double partial ----
    float acc = acc0 + acc1;
    #pragma unroll
    for (int off = 16; off > 0; off >>= 1)
        acc += __shfl_down_sync(0xffffffffu, acc, off);

    __shared__ float warpSum[4];
    __shared__ bool  isLast;
    if ((t & 31) == 0) warpSum[t >> 5] = acc;
    __syncthreads();
    if (t == 0) {
        double s = (double)warpSum[0] + (double)warpSum[1]
                 + (double)warpSum[2] + (double)warpSum[3];
        g_partials[k] = s;
        __threadfence();
        int old = atomicAdd(&g_count, 1);
        isLast = (old == nblocks - 1);
    }
    __syncthreads();
    if (!isLast) return;

    // ---- last block: deterministic final reduction ----
    __threadfence();
    double a = 0.0;
    for (int i = t; i < nblocks; i += TILE) a += g_partials[i];
    #pragma unroll
    for (int off = 16; off > 0; off >>= 1)
        a += __shfl_down_sync(0xffffffffu, a, off);

    __shared__ double ws2[4];
    if ((t & 31) == 0) ws2[t >> 5] = a;
    __syncthreads();
    if (t == 0) {
        double s = ws2[0] + ws2[1] + ws2[2] + ws2[3];
        out[0] = (float)(s / (double)n);
        g_count = 0;                      // reset for next graph replay
    }
}

extern "C" void kernel_launch(void* const* d_in, const int* in_sizes, int n_in,
                              void* d_out, int out_size) {
    const float* logits   = (const float*)d_in[0];
    const int*   rankings = (const int*)d_in[1];
    int n  = in_sizes[0];
    int nt = (n + TILE - 1) / TILE;          // 64 for N=8192
    int nblocks = nt * (nt + 1) / 2;         // 2080

    wrnl_kernel<<<nblocks, TILE>>>(logits, rankings, (float*)d_out, n, nt, nblocks);
}